// round 14
// baseline (speedup 1.0000x reference)
#include <cuda_runtime.h>
#include <math.h>

// A coefficients + device-side publish flag / completion counter.
__device__ float        g_A[9 * 4 * 12];
__device__ unsigned int g_flag = 0;
__device__ unsigned int g_cnt  = 0;

// ---------------------------------------------------------------------------
// Shuffle-based column sim (validated in R10 precompute): evolves amp (i, j)
// of U through 3 variational layers. Shuffles stay within 16-lane groups.
// ---------------------------------------------------------------------------
__device__ __forceinline__ void sim_col(float& ar, float& ai, int i,
                                        const float* vc, const float* vs,
                                        unsigned mask) {
#pragma unroll
    for (int l = 0; l < 3; l++) {
        const float* lc = vc + l * 8;
        const float* ls = vs + l * 8;
#pragma unroll
        for (int k = 0; k < 4; k++) {
            const int M = 8 >> k;
            const float cy = lc[k],     sy = ls[k];
            const float cz = lc[k + 1], sz = ls[k + 1];
            const float orr = __shfl_xor_sync(mask, ar, M);
            const float oii = __shfl_xor_sync(mask, ai, M);
            const float sgn = (i & M) ? sy : -sy;
            ar = fmaf(sgn, orr, cy * ar);
            ai = fmaf(sgn, oii, cy * ai);
            const float sg = (i & M) ? -sz : sz;
            const float rr = ar, im = ai;
            ar = fmaf(sg, im, cz * rr);
            ai = fmaf(-sg, rr, cz * im);
        }
#pragma unroll
        for (int k = 0; k < 4; k++) {
            const int CM = 8 >> k;
            const int TM = (k == 3) ? 8 : (4 >> k);
            const float orr = __shfl_xor_sync(mask, ar, TM);
            const float oii = __shfl_xor_sync(mask, ai, TM);
            if (i & CM) { ar = orr; ai = oii; }
        }
    }
}

// Factored inner product over 12-padded row: t = aw . (u2 (x) v3), 8 FMA.
__device__ __forceinline__ float dot9p(const float aw[12], float c2, float s2, float c3, float s3) {
    float m0 = fmaf(c3, aw[1], aw[0]); m0 = fmaf(s3, aw[2], m0);
    float m1 = fmaf(c3, aw[4], aw[3]); m1 = fmaf(s3, aw[5], m1);
    float m2 = fmaf(c3, aw[7], aw[6]); m2 = fmaf(s3, aw[8], m2);
    float t  = fmaf(c2, m1, m0);
    return fmaf(s2, m2, t);
}

// ---------------------------------------------------------------------------
// Single fused kernel: block 0 computes A and publishes; all blocks then run
// the R10 quad pipeline (4 images/block, grid = B/4).
// ---------------------------------------------------------------------------
__global__ __launch_bounds__(224, 4) void quanv_fused14_kernel(
    const float* __restrict__ x,     // (B,1,28,28)
    const float* __restrict__ vp,    // (3,8)
    const float* __restrict__ W,     // (10,784)
    const float* __restrict__ bias,  // (10,)
    float* __restrict__ out,         // (B,10)
    int B)
{
    const int b0   = 4 * blockIdx.x;
    const int tid  = threadIdx.x;
    const int warp = tid >> 5;
    const int lane = tid & 31;

    __shared__ __align__(16) float sA[9 * 4 * 12];
    __shared__ __align__(16) float4 feats[4][196];
    __shared__ float slog[40];
    __shared__ float slse[4];
    // block-0 scratch
    __shared__ float vcs[48];                 // vc[24], vs[24]
    __shared__ float Ur[16][16], Ui[16][16];
    __shared__ float ReO[4][16][16];

    // ================= block 0: compute A and publish =================
    if (blockIdx.x == 0) {
        if (tid < 24) {
            float ss, cc;
            __sincosf(vp[tid] * 0.5f, &ss, &cc);
            vcs[tid]      = cc;
            vcs[24 + tid] = ss;
        }
        __syncthreads();

        // pass A: warps 0-6 cover columns 0..13 (two per warp)
        {
            const int i = lane & 15;
            const int j = 2 * warp + (lane >> 4);
            float ar = (i == j) ? 1.0f : 0.0f;
            float ai = 0.0f;
            sim_col(ar, ai, i, vcs, vcs + 24, 0xffffffffu);
            Ur[i][j] = ar;
            Ui[i][j] = ai;
        }
        // pass B: warps 0-1, lanes 0-15 cover columns 14, 15
        if (warp < 2 && lane < 16) {
            const int i = lane;
            const int j = 14 + warp;
            float ar = (i == j) ? 1.0f : 0.0f;
            float ai = 0.0f;
            sim_col(ar, ai, i, vcs, vcs + 24, 0x0000ffffu);
            Ur[i][j] = ar;
            Ui[i][j] = ai;
        }
        __syncthreads();

        for (int t = tid; t < 256; t += 224) {
            const int p = t >> 4;
            const int q = t & 15;
            float acc[4] = {0.0f, 0.0f, 0.0f, 0.0f};
#pragma unroll
            for (int k = 0; k < 16; k++) {
                const float v = Ur[k][p] * Ur[k][q] + Ui[k][p] * Ui[k][q];
#pragma unroll
                for (int w = 0; w < 4; w++)
                    acc[w] += (k & (8 >> w)) ? -v : v;
            }
#pragma unroll
            for (int w = 0; w < 4; w++) ReO[w][p][q] = acc[w];
        }
        __syncthreads();

        for (int t = tid; t < 432; t += 224) {
            const int a12 = t / 48;
            const int w   = (t / 12) & 3;
            const int a34 = t % 12;
            float val = 0.0f;
            if (a34 < 9) {
                const int a0 = a12 / 3, a1 = a12 % 3;
                const int a2 = a34 / 3, a3 = a34 % 3;
                const int zm = (a0 == 1 ? 8 : 0) | (a1 == 1 ? 4 : 0) | (a2 == 1 ? 2 : 0) | (a3 == 1 ? 1 : 0);
                const int xm = (a0 == 2 ? 8 : 0) | (a1 == 2 ? 4 : 0) | (a2 == 2 ? 2 : 0) | (a3 == 2 ? 1 : 0);
                float acc = 0.0f;
#pragma unroll
                for (int p = 0; p < 16; p++) {
                    const float v = ReO[w][p][p ^ xm];
                    acc += (__popc(p & zm) & 1) ? -v : v;
                }
                val = acc * 0.0625f;
            }
            g_A[t] = val;
        }
        __syncthreads();            // all g_A stores issued
        __threadfence();            // publish to L2 before flag
        if (tid == 0) atomicExch(&g_flag, 1u);
    }

    // ---- angle phase (A-independent; overlaps block-0 compute / spin) ----
    float cs[4][8];
    if (tid < 196) {
        const int r14 = tid / 14;
        const int c14 = tid % 14;
        const int off = (2 * r14) * 28 + 2 * c14;
#pragma unroll
        for (int m = 0; m < 4; m++) {
            int b = b0 + m;
            if (b >= B) b = B - 1;               // duplicate work, writes masked later
            const float* xb = x + (size_t)b * 784;
            const float2 t2 = *reinterpret_cast<const float2*>(xb + off);
            const float2 d2 = *reinterpret_cast<const float2*>(xb + off + 28);
            __sincosf(t2.x, &cs[m][1], &cs[m][0]);
            __sincosf(t2.y, &cs[m][3], &cs[m][2]);
            __sincosf(d2.x, &cs[m][5], &cs[m][4]);
            __sincosf(d2.y, &cs[m][7], &cs[m][6]);
        }
    }

    // ---- acquire A (non-zero blocks) ----
    if (blockIdx.x != 0) {
        if (tid == 0) {
            while (atomicAdd(&g_flag, 0u) == 0u) __nanosleep(64);
            __threadfence();
        }
        __syncthreads();
    }

    for (int i = tid; i < 9 * 4 * 12; i += 224)
        sA[i] = g_A[i];
    __syncthreads();

    // ================= R10 quad pipeline =================
    if (tid < 196) {
        float e[4][4];
#pragma unroll
        for (int m = 0; m < 4; m++)
#pragma unroll
            for (int w = 0; w < 4; w++) e[m][w] = 0.0f;

#pragma unroll
        for (int i = 0; i < 9; i++) {
            float ga[4];
#pragma unroll
            for (int m = 0; m < 4; m++) {
                const int iu = i / 3, iv = i % 3;
                const float u = (iu == 0) ? 1.0f : (iu == 1 ? cs[m][0] : cs[m][1]);
                const float v = (iv == 0) ? 1.0f : (iv == 1 ? cs[m][2] : cs[m][3]);
                ga[m] = u * v;
            }
#pragma unroll
            for (int w = 0; w < 4; w++) {
                float aw[12];
#pragma unroll
                for (int q = 0; q < 3; q++)
                    *reinterpret_cast<float4*>(aw + 4 * q) =
                        *reinterpret_cast<const float4*>(&sA[(i * 4 + w) * 12 + 4 * q]);
#pragma unroll
                for (int m = 0; m < 4; m++) {
                    const float t = dot9p(aw, cs[m][4], cs[m][5], cs[m][6], cs[m][7]);
                    e[m][w] = fmaf(ga[m], t, e[m][w]);
                }
            }
        }

#pragma unroll
        for (int m = 0; m < 4; m++)
            feats[m][tid] = make_float4(e[m][0], e[m][1], e[m][2], e[m][3]);
    }
    __syncthreads();

    // ---- warp-GEMM logits: 40 tasks (img,class) over 7 warps ----
#pragma unroll
    for (int r = 0; r < 6; r++) {
        const int task = warp + 7 * r;
        if (task < 40) {
            const int img = task / 10;
            const int c   = task % 10;
            const float* wrow = W + c * 784;
            float acc = 0.0f;
#pragma unroll
            for (int k = 0; k < 6; k++) {
                const int p = 32 * k + lane;
                const float4 fv = feats[img][p];
                const float4 wv = *reinterpret_cast<const float4*>(wrow + 4 * p);
                acc = fmaf(fv.x, wv.x, acc);
                acc = fmaf(fv.y, wv.y, acc);
                acc = fmaf(fv.z, wv.z, acc);
                acc = fmaf(fv.w, wv.w, acc);
            }
            if (lane < 4) {
                const int p = 192 + lane;
                const float4 fv = feats[img][p];
                const float4 wv = *reinterpret_cast<const float4*>(wrow + 4 * p);
                acc = fmaf(fv.x, wv.x, acc);
                acc = fmaf(fv.y, wv.y, acc);
                acc = fmaf(fv.z, wv.z, acc);
                acc = fmaf(fv.w, wv.w, acc);
            }
#pragma unroll
            for (int o = 16; o > 0; o >>= 1)
                acc += __shfl_xor_sync(0xffffffffu, acc, o);
            if (lane == 0) slog[task] = acc + bias[c];
        }
    }
    __syncthreads();

    if (tid < 4) {
        const float* l = slog + 10 * tid;
        float mx = l[0];
#pragma unroll
        for (int c = 1; c < 10; c++) mx = fmaxf(mx, l[c]);
        float se = 0.0f;
#pragma unroll
        for (int c = 0; c < 10; c++) se += expf(l[c] - mx);
        slse[tid] = mx + logf(se);
    }
    __syncthreads();

    if (tid < 40) {
        const int img = tid / 10;
        const int b = b0 + img;
        if (b < B)
            out[(size_t)b * 10 + (tid % 10)] = slog[tid] - slse[img];
    }

    // ---- reset flag/counter so every call does identical work ----
    if (tid == 0) {
        __threadfence();
        const unsigned old = atomicAdd(&g_cnt, 1u);
        if (old == (unsigned)gridDim.x - 1u) {
            g_cnt  = 0u;
            g_flag = 0u;
            __threadfence();
        }
    }
}

extern "C" void kernel_launch(void* const* d_in, const int* in_sizes, int n_in,
                              void* d_out, int out_size) {
    const float* x    = (const float*)d_in[0];   // (B,1,28,28)
    const float* vp   = (const float*)d_in[1];   // (3,8)
    const float* W    = (const float*)d_in[2];   // (10,784)
    const float* bias = (const float*)d_in[3];   // (10,)
    float* out = (float*)d_out;

    const int B = in_sizes[0] / 784;
    quanv_fused14_kernel<<<(B + 3) / 4, 224>>>(x, vp, W, bias, out, B);
}

// round 16
// speedup vs baseline: 1.1929x; 1.1929x over previous
#include <cuda_runtime.h>
#include <math.h>

// Coefficient tensor, layout [i(a12)][w][12]: j at 0..8, pad 9..11.
__device__ float g_A[9 * 4 * 12];

// ---------------------------------------------------------------------------
// Fast precompute kernel (R10): 256 threads = (amp i = tid%16, col j = tid/16),
// gates via __shfl_xor_sync; then ReO and the multilinear coefficients.
// ---------------------------------------------------------------------------
__global__ void precompute_A_fast_kernel(const float* __restrict__ vp) {
    __shared__ float vc[24], vs[24];
    __shared__ float Ur[16][16], Ui[16][16];
    __shared__ float ReO[4][16][16];

    const int tid = threadIdx.x;
    const int i   = tid & 15;
    const int j   = tid >> 4;

    if (tid < 24) {
        float ss, cc;
        __sincosf(vp[tid] * 0.5f, &ss, &cc);
        vc[tid] = cc;
        vs[tid] = ss;
    }
    __syncthreads();

    float ar = (i == j) ? 1.0f : 0.0f;
    float ai = 0.0f;

#pragma unroll
    for (int l = 0; l < 3; l++) {
        const float* lc = vc + l * 8;
        const float* ls = vs + l * 8;
#pragma unroll
        for (int k = 0; k < 4; k++) {
            const int M = 8 >> k;
            const float cy = lc[k],     sy = ls[k];
            const float cz = lc[k + 1], sz = ls[k + 1];
            const float orr = __shfl_xor_sync(0xffffffffu, ar, M);
            const float oii = __shfl_xor_sync(0xffffffffu, ai, M);
            const float sgn = (i & M) ? sy : -sy;
            ar = fmaf(sgn, orr, cy * ar);
            ai = fmaf(sgn, oii, cy * ai);
            const float sg = (i & M) ? -sz : sz;
            const float rr = ar, im = ai;
            ar = fmaf(sg, im, cz * rr);
            ai = fmaf(-sg, rr, cz * im);
        }
#pragma unroll
        for (int k = 0; k < 4; k++) {
            const int CM = 8 >> k;
            const int TM = (k == 3) ? 8 : (4 >> k);
            const float orr = __shfl_xor_sync(0xffffffffu, ar, TM);
            const float oii = __shfl_xor_sync(0xffffffffu, ai, TM);
            if (i & CM) { ar = orr; ai = oii; }
        }
    }

    Ur[i][j] = ar;
    Ui[i][j] = ai;
    __syncthreads();

    {
        const int p = tid >> 4;
        const int q = tid & 15;
        float acc[4] = {0.0f, 0.0f, 0.0f, 0.0f};
#pragma unroll
        for (int k = 0; k < 16; k++) {
            const float t = Ur[k][p] * Ur[k][q] + Ui[k][p] * Ui[k][q];
#pragma unroll
            for (int w = 0; w < 4; w++)
                acc[w] += (k & (8 >> w)) ? -t : t;
        }
#pragma unroll
        for (int w = 0; w < 4; w++) ReO[w][p][q] = acc[w];
    }
    __syncthreads();

    for (int t = tid; t < 432; t += 256) {
        const int a12 = t / 48;
        const int w   = (t / 12) & 3;
        const int a34 = t % 12;
        float val = 0.0f;
        if (a34 < 9) {
            const int a0 = a12 / 3, a1 = a12 % 3;
            const int a2 = a34 / 3, a3 = a34 % 3;
            const int zm = (a0 == 1 ? 8 : 0) | (a1 == 1 ? 4 : 0) | (a2 == 1 ? 2 : 0) | (a3 == 1 ? 1 : 0);
            const int xm = (a0 == 2 ? 8 : 0) | (a1 == 2 ? 4 : 0) | (a2 == 2 ? 2 : 0) | (a3 == 2 ? 1 : 0);
            float acc = 0.0f;
#pragma unroll
            for (int p = 0; p < 16; p++) {
                const float v = ReO[w][p][p ^ xm];
                acc += (__popc(p & zm) & 1) ? -v : v;
            }
            val = acc * 0.0625f;
        }
        g_A[t] = val;
    }
}

// Factored inner product over 12-padded row: t = aw . (u2 (x) v3), 8 FMA.
__device__ __forceinline__ float dot9p(const float aw[12], float c2, float s2, float c3, float s3) {
    float m0 = fmaf(c3, aw[1], aw[0]); m0 = fmaf(s3, aw[2], m0);
    float m1 = fmaf(c3, aw[4], aw[3]); m1 = fmaf(s3, aw[5], m1);
    float m2 = fmaf(c3, aw[7], aw[6]); m2 = fmaf(s3, aw[8], m2);
    float t  = fmaf(c2, m1, m0);
    return fmaf(s2, m2, t);
}

// ---------------------------------------------------------------------------
// Main fused kernel (R10 datapath): one block per 4 IMAGES; contraction ->
// feats smem -> class-pair warp-GEMM with combined 2-value butterfly ->
// log_softmax.
// ---------------------------------------------------------------------------
__global__ __launch_bounds__(224, 4) void quanv_fused16_kernel(
    const float* __restrict__ x,     // (B,1,28,28)
    const float* __restrict__ W,     // (10,784)
    const float* __restrict__ bias,  // (10,)
    float* __restrict__ out,         // (B,10)
    int B)
{
    const int b0   = 4 * blockIdx.x;
    const int tid  = threadIdx.x;
    const int warp = tid >> 5;
    const int lane = tid & 31;

    __shared__ __align__(16) float sA[9 * 4 * 12];
    __shared__ __align__(16) float4 feats[4][196];
    __shared__ float slog[40];
    __shared__ float slse[4];

    for (int i = tid; i < 9 * 4 * 12; i += 224)
        sA[i] = g_A[i];
    __syncthreads();

    if (tid < 196) {
        const int r14 = tid / 14;
        const int c14 = tid % 14;
        const int off = (2 * r14) * 28 + 2 * c14;

        float cs[4][8];
#pragma unroll
        for (int m = 0; m < 4; m++) {
            int b = b0 + m;
            if (b >= B) b = B - 1;               // duplicate work, writes masked later
            const float* xb = x + (size_t)b * 784;
            const float2 t2 = *reinterpret_cast<const float2*>(xb + off);
            const float2 d2 = *reinterpret_cast<const float2*>(xb + off + 28);
            __sincosf(t2.x, &cs[m][1], &cs[m][0]);
            __sincosf(t2.y, &cs[m][3], &cs[m][2]);
            __sincosf(d2.x, &cs[m][5], &cs[m][4]);
            __sincosf(d2.y, &cs[m][7], &cs[m][6]);
        }

        float e[4][4];
#pragma unroll
        for (int m = 0; m < 4; m++)
#pragma unroll
            for (int w = 0; w < 4; w++) e[m][w] = 0.0f;

#pragma unroll
        for (int i = 0; i < 9; i++) {
            float ga[4];
#pragma unroll
            for (int m = 0; m < 4; m++) {
                const int iu = i / 3, iv = i % 3;
                const float u = (iu == 0) ? 1.0f : (iu == 1 ? cs[m][0] : cs[m][1]);
                const float v = (iv == 0) ? 1.0f : (iv == 1 ? cs[m][2] : cs[m][3]);
                ga[m] = u * v;
            }
#pragma unroll
            for (int w = 0; w < 4; w++) {
                float aw[12];
#pragma unroll
                for (int q = 0; q < 3; q++)
                    *reinterpret_cast<float4*>(aw + 4 * q) =
                        *reinterpret_cast<const float4*>(&sA[(i * 4 + w) * 12 + 4 * q]);
#pragma unroll
                for (int m = 0; m < 4; m++) {
                    const float t = dot9p(aw, cs[m][4], cs[m][5], cs[m][6], cs[m][7]);
                    e[m][w] = fmaf(ga[m], t, e[m][w]);
                }
            }
        }

#pragma unroll
        for (int m = 0; m < 4; m++)
            feats[m][tid] = make_float4(e[m][0], e[m][1], e[m][2], e[m][3]);
    }
    __syncthreads();

    // ---- warp-GEMM logits: 20 (img, class-pair) tasks over 7 warps ----
#pragma unroll
    for (int r = 0; r < 3; r++) {
        const int task = warp + 7 * r;
        if (task < 20) {
            const int img = task / 5;
            const int c0  = 2 * (task % 5);
            const float* w0 = W + c0 * 784;
            const float* w1 = w0 + 784;
            float acc0 = 0.0f, acc1 = 0.0f;
#pragma unroll
            for (int k = 0; k < 6; k++) {
                const int p = 32 * k + lane;
                const float4 fv = feats[img][p];
                const float4 wa = *reinterpret_cast<const float4*>(w0 + 4 * p);
                const float4 wb = *reinterpret_cast<const float4*>(w1 + 4 * p);
                acc0 = fmaf(fv.x, wa.x, acc0);
                acc0 = fmaf(fv.y, wa.y, acc0);
                acc0 = fmaf(fv.z, wa.z, acc0);
                acc0 = fmaf(fv.w, wa.w, acc0);
                acc1 = fmaf(fv.x, wb.x, acc1);
                acc1 = fmaf(fv.y, wb.y, acc1);
                acc1 = fmaf(fv.z, wb.z, acc1);
                acc1 = fmaf(fv.w, wb.w, acc1);
            }
            if (lane < 4) {
                const int p = 192 + lane;
                const float4 fv = feats[img][p];
                const float4 wa = *reinterpret_cast<const float4*>(w0 + 4 * p);
                const float4 wb = *reinterpret_cast<const float4*>(w1 + 4 * p);
                acc0 = fmaf(fv.x, wa.x, acc0);
                acc0 = fmaf(fv.y, wa.y, acc0);
                acc0 = fmaf(fv.z, wa.z, acc0);
                acc0 = fmaf(fv.w, wa.w, acc0);
                acc1 = fmaf(fv.x, wb.x, acc1);
                acc1 = fmaf(fv.y, wb.y, acc1);
                acc1 = fmaf(fv.z, wb.z, acc1);
                acc1 = fmaf(fv.w, wb.w, acc1);
            }
            // Combined 2-value reduction: fold 32->16 for each, pack into
            // lane halves, then one 16-lane butterfly reduces both.
            acc0 += __shfl_xor_sync(0xffffffffu, acc0, 16);
            acc1 += __shfl_xor_sync(0xffffffffu, acc1, 16);
            float v = (lane < 16) ? acc0 : acc1;
#pragma unroll
            for (int o = 8; o > 0; o >>= 1)
                v += __shfl_xor_sync(0xffffffffu, v, o);
            if (lane == 0)  slog[img * 10 + c0]     = v + bias[c0];
            if (lane == 16) slog[img * 10 + c0 + 1] = v + bias[c0 + 1];
        }
    }
    __syncthreads();

    if (tid < 4) {
        const float* l = slog + 10 * tid;
        float mx = l[0];
#pragma unroll
        for (int c = 1; c < 10; c++) mx = fmaxf(mx, l[c]);
        float se = 0.0f;
#pragma unroll
        for (int c = 0; c < 10; c++) se += expf(l[c] - mx);
        slse[tid] = mx + logf(se);
    }
    __syncthreads();

    if (tid < 40) {
        const int img = tid / 10;
        const int b = b0 + img;
        if (b < B)
            out[(size_t)b * 10 + (tid % 10)] = slog[tid] - slse[img];
    }
}

extern "C" void kernel_launch(void* const* d_in, const int* in_sizes, int n_in,
                              void* d_out, int out_size) {
    const float* x    = (const float*)d_in[0];   // (B,1,28,28)
    const float* vp   = (const float*)d_in[1];   // (3,8)
    const float* W    = (const float*)d_in[2];   // (10,784)
    const float* bias = (const float*)d_in[3];   // (10,)
    float* out = (float*)d_out;

    const int B = in_sizes[0] / 784;
    precompute_A_fast_kernel<<<1, 256>>>(vp);
    quanv_fused16_kernel<<<(B + 3) / 4, 224>>>(x, W, bias, out, B);
}